// round 5
// baseline (speedup 1.0000x reference)
#include <cuda_runtime.h>

#define BB 2
#define CC 128
#define HH 128
#define WWD 128
#define HW 16384
#define GG 8
#define CG 16
#define KK9 9
#define OMC 216
#define KDIM 1152
#define KC 16

typedef unsigned long long ull;

// ---------------- static scratch (no allocation allowed) ----------------
__device__ float g_feat_up [BB*CC*HW];   // bilinear-upsampled feat_s
__device__ float g_feat_arm[BB*CC*HW];   // relu(conv1x1 fsm)
__device__ float g_offf    [BB*CC*HW];   // offset_feat
__device__ float g_om      [BB*OMC*HW];  // conv_offset_mask output
__device__ float g_pooled  [BB*CC];
__device__ float g_scale   [BB*CC];      // 1 + sigmoid(relu(..))
__device__ float g_WT_fsm  [CC*CC];        // [c][o]
__device__ float g_WT_off  [2*CC*CC];      // [c][o], c in [0,256)
__device__ float g_WT_om   [KDIM*256];     // [tap*128+c][o(pad 256)]
__device__ float g_WT_dcn  [KDIM*CC];      // [(g*9+kk)*16+cg][o]

// ---------------- f32x2 packed math helpers ----------------
__device__ __forceinline__ ull ffma2(ull a, ull b, ull c){
    ull d;
    asm("fma.rn.f32x2 %0, %1, %2, %3;" : "=l"(d) : "l"(a), "l"(b), "l"(c));
    return d;
}
__device__ __forceinline__ ull splat2(float a){
    ull d;
    asm("mov.b64 %0, {%1, %1};" : "=l"(d) : "f"(a));
    return d;
}
__device__ __forceinline__ float2 unpack2(ull v){
    float2 r;
    asm("mov.b64 {%0, %1}, %2;" : "=f"(r.x), "=f"(r.y) : "l"(v));
    return r;
}

// ---------------- shared GEMM inner: 128o x 128p tile, K-chunk of 16 ----------------
// Ws: [KC][128] (o minor), Xs: [KC][128] (p minor). Thread: 8 o x 8 p.
__device__ __forceinline__ void mma_chunk(const float* __restrict__ Ws,
                                          const float* __restrict__ Xs,
                                          ull acc[8][4], int to, int tp){
#pragma unroll
    for (int k = 0; k < KC; k++){
        const ulonglong2* bp = reinterpret_cast<const ulonglong2*>(Xs + k*128 + tp*8);
        ulonglong2 b01 = bp[0];
        ulonglong2 b23 = bp[1];
        const float4* ap = reinterpret_cast<const float4*>(Ws + k*128 + to*8);
        float4 a0 = ap[0], a1 = ap[1];
        float av[8] = {a0.x,a0.y,a0.z,a0.w,a1.x,a1.y,a1.z,a1.w};
#pragma unroll
        for (int j = 0; j < 8; j++){
            ull a2 = splat2(av[j]);
            acc[j][0] = ffma2(a2, b01.x, acc[j][0]);
            acc[j][1] = ffma2(a2, b01.y, acc[j][1]);
            acc[j][2] = ffma2(a2, b23.x, acc[j][2]);
            acc[j][3] = ffma2(a2, b23.y, acc[j][3]);
        }
    }
}

// ---------------- weight transposes ----------------
__global__ void k_T_fsm(const float* __restrict__ w){
    int i = blockIdx.x*256 + threadIdx.x;
    if (i < CC*CC){ int o = i >> 7, c = i & 127; g_WT_fsm[c*CC + o] = w[i]; }
}
__global__ void k_T_off(const float* __restrict__ w){   // w: [128][256]
    int i = blockIdx.x*256 + threadIdx.x;
    if (i < CC*2*CC){ int o = i >> 8, c = i & 255; g_WT_off[c*CC + o] = w[i]; }
}
__global__ void k_T_om(const float* __restrict__ w){    // w: [216][128][3][3]
    int i = blockIdx.x*256 + threadIdx.x;
    if (i < KDIM*256){
        int o = i & 255, kidx = i >> 8;
        int tap = kidx >> 7, c = kidx & 127;
        g_WT_om[i] = (o < OMC) ? w[(o*CC + c)*KK9 + tap] : 0.f;
    }
}
__global__ void k_T_dcn(const float* __restrict__ w){   // w: [128][128][3][3]
    int i = blockIdx.x*256 + threadIdx.x;
    if (i < KDIM*CC){
        int o = i & 127, kidx = i >> 7;
        int gk = kidx >> 4, cg = kidx & 15;
        int g = gk/9, kk = gk - g*9;
        int c = g*CG + cg;
        g_WT_dcn[i] = w[(o*CC + c)*KK9 + kk];
    }
}

// ---------------- pooled mean + attention scale ----------------
__global__ void k_pool(const float* __restrict__ fl){
    int bc = blockIdx.x, t = threadIdx.x;
    const float* p = fl + bc*HW;
    float s = 0.f;
    for (int i = t; i < HW; i += 256) s += p[i];
    __shared__ float red[256];
    red[t] = s; __syncthreads();
#pragma unroll
    for (int o = 128; o > 0; o >>= 1){
        if (t < o) red[t] += red[t + o];
        __syncthreads();
    }
    if (t == 0) g_pooled[bc] = red[0] * (1.f/(float)HW);
}
__global__ void k_atten(const float* __restrict__ w_atten){
    int b = blockIdx.x, o = threadIdx.x;
    __shared__ float pl[CC];
    pl[o] = g_pooled[b*CC + o];
    __syncthreads();
    float s = 0.f;
    const float* wr = w_atten + o*CC;
    for (int c = 0; c < CC; c++) s = fmaf(pl[c], wr[c], s);
    s = fmaxf(s, 0.f);
    g_scale[b*CC + o] = 1.f + 1.f/(1.f + __expf(-s));
}

// ---------------- bilinear upsample (jax.image.resize semantics) ----------------
__global__ void k_upsample(const float* __restrict__ fs){
    int idx = blockIdx.x*256 + threadIdx.x;          // exact grid
    int x = idx & 127, y = (idx >> 7) & 127, bc = idx >> 14;
    float fy = y*0.5f - 0.25f, fx = x*0.5f - 0.25f;
    float y0f = floorf(fy), x0f = floorf(fx);
    float wy = fy - y0f, wx = fx - x0f;
    int y0 = (int)y0f, x0 = (int)x0f;
    int y0c = max(y0, 0), y1c = min(y0 + 1, 63);
    int x0c = max(x0, 0), x1c = min(x0 + 1, 63);
    const float* s = fs + bc*4096;
    float v00 = s[y0c*64 + x0c], v01 = s[y0c*64 + x1c];
    float v10 = s[y1c*64 + x0c], v11 = s[y1c*64 + x1c];
    g_feat_up[idx] = (1.f-wy)*((1.f-wx)*v00 + wx*v01) + wy*((1.f-wx)*v10 + wx*v11);
}

// ---------------- GEMM 1: feat_arm = relu(Wfsm @ (feat_l * scale_c)) ----------------
__global__ __launch_bounds__(256,2) void k_gemm_fsm(const float* __restrict__ feat_l){
    __shared__ float Ws[KC*128], Xs[KC*128], ssc[CC];
    int y = blockIdx.x, b = blockIdx.y, t = threadIdx.x;
    if (t < CC) ssc[t] = g_scale[b*CC + t];
    int to = t >> 4, tp = t & 15, r = t >> 4, q8 = (t & 15)*8;
    ull acc[8][4];
#pragma unroll
    for (int j = 0; j < 8; j++) for (int i = 0; i < 4; i++) acc[j][i] = 0ull;
#pragma unroll 1
    for (int k0 = 0; k0 < CC; k0 += KC){
        __syncthreads();
        {
            const float4* wp = reinterpret_cast<const float4*>(g_WT_fsm + (k0+r)*128 + q8);
            float4 w0 = wp[0], w1 = wp[1];
            *reinterpret_cast<float4*>(Ws + r*128 + q8)     = w0;
            *reinterpret_cast<float4*>(Ws + r*128 + q8 + 4) = w1;
        }
        {
            int c = k0 + r;
            float sc = ssc[c];
            const float4* xp = reinterpret_cast<const float4*>(feat_l + ((b*CC+c)*HH + y)*WWD + q8);
            float4 v0 = xp[0], v1 = xp[1];
            v0.x*=sc; v0.y*=sc; v0.z*=sc; v0.w*=sc;
            v1.x*=sc; v1.y*=sc; v1.z*=sc; v1.w*=sc;
            *reinterpret_cast<float4*>(Xs + r*128 + q8)     = v0;
            *reinterpret_cast<float4*>(Xs + r*128 + q8 + 4) = v1;
        }
        __syncthreads();
        mma_chunk(Ws, Xs, acc, to, tp);
    }
#pragma unroll
    for (int j = 0; j < 8; j++){
        int o = to*8 + j;
        float2* dst = reinterpret_cast<float2*>(g_feat_arm + ((b*CC+o)*HH + y)*WWD + tp*8);
#pragma unroll
        for (int i2 = 0; i2 < 4; i2++){
            float2 v = unpack2(acc[j][i2]);
            v.x = fmaxf(v.x, 0.f); v.y = fmaxf(v.y, 0.f);
            dst[i2] = v;
        }
    }
}

// ---------------- GEMM 2: offset_feat = relu(Woff @ [feat_arm ; 2*feat_up]) ----------------
__global__ __launch_bounds__(256,2) void k_gemm_off(){
    __shared__ float Ws[KC*128], Xs[KC*128];
    int y = blockIdx.x, b = blockIdx.y, t = threadIdx.x;
    int to = t >> 4, tp = t & 15, r = t >> 4, q8 = (t & 15)*8;
    ull acc[8][4];
#pragma unroll
    for (int j = 0; j < 8; j++) for (int i = 0; i < 4; i++) acc[j][i] = 0ull;
#pragma unroll 1
    for (int k0 = 0; k0 < 2*CC; k0 += KC){
        __syncthreads();
        {
            const float4* wp = reinterpret_cast<const float4*>(g_WT_off + (k0+r)*128 + q8);
            float4 w0 = wp[0], w1 = wp[1];
            *reinterpret_cast<float4*>(Ws + r*128 + q8)     = w0;
            *reinterpret_cast<float4*>(Ws + r*128 + q8 + 4) = w1;
        }
        {
            int c = k0 + r;
            const float* base; float sc;
            if (c < CC){ base = g_feat_arm + ((b*CC + c)*HH + y)*WWD;        sc = 1.f; }
            else       { base = g_feat_up  + ((b*CC + (c-CC))*HH + y)*WWD;   sc = 2.f; }
            const float4* xp = reinterpret_cast<const float4*>(base + q8);
            float4 v0 = xp[0], v1 = xp[1];
            v0.x*=sc; v0.y*=sc; v0.z*=sc; v0.w*=sc;
            v1.x*=sc; v1.y*=sc; v1.z*=sc; v1.w*=sc;
            *reinterpret_cast<float4*>(Xs + r*128 + q8)     = v0;
            *reinterpret_cast<float4*>(Xs + r*128 + q8 + 4) = v1;
        }
        __syncthreads();
        mma_chunk(Ws, Xs, acc, to, tp);
    }
#pragma unroll
    for (int j = 0; j < 8; j++){
        int o = to*8 + j;
        float2* dst = reinterpret_cast<float2*>(g_offf + ((b*CC+o)*HH + y)*WWD + tp*8);
#pragma unroll
        for (int i2 = 0; i2 < 4; i2++){
            float2 v = unpack2(acc[j][i2]);
            v.x = fmaxf(v.x, 0.f); v.y = fmaxf(v.y, 0.f);
            dst[i2] = v;
        }
    }
}

// ---------------- GEMM 3: om = Wom(3x3) * offset_feat + bias (implicit shifted GEMM) ----------------
__global__ __launch_bounds__(256,2) void k_gemm_om(const float* __restrict__ b_offmask){
    __shared__ float Ws[KC*128], Xs[KC*128];
    int y = blockIdx.x, b = blockIdx.y, t = threadIdx.x;
    int o0 = blockIdx.z * 128;
    int to = t >> 4, tp = t & 15, r = t >> 4, q8 = (t & 15)*8;
    ull acc[8][4];
#pragma unroll
    for (int j = 0; j < 8; j++) for (int i = 0; i < 4; i++) acc[j][i] = 0ull;
#pragma unroll 1
    for (int k0 = 0; k0 < KDIM; k0 += KC){
        int tap = k0 >> 7;                       // kidx = tap*128 + c; KC|128 so tap fixed per chunk
        int ty = tap/3 - 1, tx = tap - (tap/3)*3 - 1;
        __syncthreads();
        {
            const float4* wp = reinterpret_cast<const float4*>(g_WT_om + (k0+r)*256 + o0 + q8);
            float4 w0 = wp[0], w1 = wp[1];
            *reinterpret_cast<float4*>(Ws + r*128 + q8)     = w0;
            *reinterpret_cast<float4*>(Ws + r*128 + q8 + 4) = w1;
        }
        {
            int c = (k0 & 127) + r;
            int gy = y + ty;
            bool rowok = (gy >= 0) && (gy < HH);
            const float* rowp = g_offf + ((b*CC + c)*HH + gy)*WWD;
#pragma unroll
            for (int i = 0; i < 8; i++){
                int gx = q8 + i + tx;
                float v = 0.f;
                if (rowok && gx >= 0 && gx < WWD) v = rowp[gx];
                Xs[r*128 + q8 + i] = v;
            }
        }
        __syncthreads();
        mma_chunk(Ws, Xs, acc, to, tp);
    }
#pragma unroll
    for (int j = 0; j < 8; j++){
        int o = o0 + to*8 + j;
        if (o < OMC){
            float bias = b_offmask[o];
            float2* dst = reinterpret_cast<float2*>(g_om + (b*OMC + o)*HW + y*WWD + tp*8);
#pragma unroll
            for (int i2 = 0; i2 < 4; i2++){
                float2 v = unpack2(acc[j][i2]);
                v.x += bias; v.y += bias;
                dst[i2] = v;
            }
        }
    }
}

// ---------------- GEMM 4: modulated deformable conv + relu + residual -> d_out ----------------
__global__ __launch_bounds__(256,2) void k_gemm_dcn(const float* __restrict__ feat_l,
                                                    const float* __restrict__ b_dcn,
                                                    float* __restrict__ out){
    __shared__ float Ws[KC*128], Xs[KC*128];
    __shared__ float4 swt[128];
    __shared__ int4  sof[128];
    int y = blockIdx.x, b = blockIdx.y, t = threadIdx.x;
    int to = t >> 4, tp = t & 15, r = t >> 4, q8 = (t & 15)*8;
    ull acc[8][4];
#pragma unroll
    for (int j = 0; j < 8; j++) for (int i = 0; i < 4; i++) acc[j][i] = 0ull;
#pragma unroll 1
    for (int gk = 0; gk < GG*KK9; gk++){         // one (g,kk) per K-chunk of 16 (= all cg)
        int g = gk/9, kk = gk - g*9;
        __syncthreads();
        {
            const float4* wp = reinterpret_cast<const float4*>(g_WT_dcn + (gk*16 + r)*128 + q8);
            float4 w0 = wp[0], w1 = wp[1];
            *reinterpret_cast<float4*>(Ws + r*128 + q8)     = w0;
            *reinterpret_cast<float4*>(Ws + r*128 + q8 + 4) = w1;
        }
        if (t < 128){
            int x = t;
            const float* omp = g_om + b*OMC*HW + y*WWD + x;
            float dy = omp[(g*18 + kk*2    )*HW];
            float dx = omp[(g*18 + kk*2 + 1)*HW];
            float mv = omp[(144 + g*9 + kk )*HW];
            float m  = 1.f/(1.f + __expf(-mv));
            float py = (float)(y + kk/3 - 1) + dy;
            float px = (float)(x + (kk - (kk/3)*3) - 1) + dx;
            float y0f = floorf(py), x0f = floorf(px);
            float ly = py - y0f, lx = px - x0f;
            int y0 = (int)y0f, x0 = (int)x0f;
            float vy0 = (y0 >=  0 && y0 < HH    ) ? 1.f : 0.f;
            float vy1 = (y0 >= -1 && y0 < HH - 1) ? 1.f : 0.f;
            float vx0 = (x0 >=  0 && x0 < WWD    ) ? 1.f : 0.f;
            float vx1 = (x0 >= -1 && x0 < WWD - 1) ? 1.f : 0.f;
            float omy = 1.f - ly, omx = 1.f - lx;
            float4 w;
            w.x = omy*omx*vy0*vx0*m;
            w.y = omy*lx *vy0*vx1*m;
            w.z = ly *omx*vy1*vx0*m;
            w.w = ly *lx *vy1*vx1*m;
            int y0c = min(max(y0,0),HH-1),   y1c = min(max(y0+1,0),HH-1);
            int x0c = min(max(x0,0),WWD-1),  x1c = min(max(x0+1,0),WWD-1);
            sof[x] = make_int4(y0c*WWD + x0c, y0c*WWD + x1c, y1c*WWD + x0c, y1c*WWD + x1c);
            swt[x] = w;
        }
        __syncthreads();
        {
            int cg = r;   // k-row within chunk == cg
            const float* fp = g_feat_up + (b*CC + g*CG + cg)*HW;
#pragma unroll
            for (int i = 0; i < 8; i++){
                int px = q8 + i;
                int4  o4 = sof[px];
                float4 w4 = swt[px];
                Xs[cg*128 + px] = w4.x*fp[o4.x] + w4.y*fp[o4.y] + w4.z*fp[o4.z] + w4.w*fp[o4.w];
            }
        }
        __syncthreads();
        mma_chunk(Ws, Xs, acc, to, tp);
    }
#pragma unroll
    for (int j = 0; j < 8; j++){
        int o = to*8 + j;
        float bias = b_dcn[o];
        int base = ((b*CC + o)*HH + y)*WWD + tp*8;
        const float2* flp = reinterpret_cast<const float2*>(feat_l + base);
        float2* dst = reinterpret_cast<float2*>(out + base);
#pragma unroll
        for (int i2 = 0; i2 < 4; i2++){
            float2 v  = unpack2(acc[j][i2]);
            float2 fl = flp[i2];
            v.x = fmaxf(v.x + bias, 0.f) + fl.x;
            v.y = fmaxf(v.y + bias, 0.f) + fl.y;
            dst[i2] = v;
        }
    }
}

// ---------------- launcher ----------------
extern "C" void kernel_launch(void* const* d_in, const int* in_sizes, int n_in,
                              void* d_out, int out_size){
    (void)in_sizes; (void)n_in; (void)out_size;
    const float* feat_l    = (const float*)d_in[0];
    const float* feat_s    = (const float*)d_in[1];
    const float* w_atten   = (const float*)d_in[2];
    const float* w_fsm     = (const float*)d_in[3];
    const float* w_off     = (const float*)d_in[4];
    const float* w_offmask = (const float*)d_in[5];
    const float* b_offmask = (const float*)d_in[6];
    const float* w_dcn     = (const float*)d_in[7];
    const float* b_dcn     = (const float*)d_in[8];
    float* out = (float*)d_out;

    k_T_fsm<<<64, 256>>>(w_fsm);
    k_T_off<<<128, 256>>>(w_off);
    k_T_om<<<1152, 256>>>(w_offmask);
    k_T_dcn<<<576, 256>>>(w_dcn);
    k_pool<<<BB*CC, 256>>>(feat_l);
    k_atten<<<BB, CC>>>(w_atten);
    k_upsample<<<(BB*CC*HW)/256, 256>>>(feat_s);
    k_gemm_fsm<<<dim3(HH, BB), 256>>>(feat_l);
    k_gemm_off<<<dim3(HH, BB), 256>>>();
    k_gemm_om<<<dim3(HH, BB, 2), 256>>>(b_offmask);
    k_gemm_dcn<<<dim3(HH, BB), 256>>>(feat_l, b_dcn, out);
}

// round 7
// speedup vs baseline: 2.4464x; 2.4464x over previous
#include <cuda_runtime.h>

#define BB 2
#define CC 128
#define HH 128
#define WWD 128
#define HW 16384
#define GG 8
#define CG 16
#define KK9 9
#define OMC 216
#define KDIM 1152
#define KC 16

typedef unsigned long long ull;

// ---------------- static scratch (no allocation allowed) ----------------
__device__ float g_feat_up [BB*CC*HW];
__device__ float g_feat_arm[BB*CC*HW];
__device__ float g_offf    [BB*CC*HW];
__device__ float g_om      [BB*OMC*HW];
__device__ float g_pooled  [BB*CC];
__device__ float g_scale   [BB*CC];
__device__ float g_WT_fsm  [CC*CC];        // [c][o]
__device__ float g_WT_off  [2*CC*CC];      // [c][o]
__device__ float g_WT_om   [KDIM*256];     // [tap*128+c][o pad 256]
__device__ float g_WT_dcn  [KDIM*CC];      // [(g*9+kk)*16+cg][o]

// ---------------- helpers ----------------
__device__ __forceinline__ ull ffma2(ull a, ull b, ull c){
    ull d;
    asm("fma.rn.f32x2 %0, %1, %2, %3;" : "=l"(d) : "l"(a), "l"(b), "l"(c));
    return d;
}
__device__ __forceinline__ ull splat2(float a){
    ull d;
    asm("mov.b64 %0, {%1, %1};" : "=l"(d) : "f"(a));
    return d;
}
__device__ __forceinline__ float2 unpack2(ull v){
    float2 r;
    asm("mov.b64 {%0, %1}, %2;" : "=f"(r.x), "=f"(r.y) : "l"(v));
    return r;
}
// 16B-unit XOR swizzle: byte -> byte ^ (((byte>>7)&1)<<4). Conflict-free for
// stride-32B lane patterns. Preserves 16B alignment.
__device__ __forceinline__ int swz(int b){ return b ^ ((b >> 3) & 16); }

// ---------------- inner MMA: 128o x 128p tile, K-chunk 16, swizzled smem ----
__device__ __forceinline__ void mma_chunk(const char* __restrict__ Ws,
                                          const char* __restrict__ Xs,
                                          ull acc[8][4],
                                          int oA0, int oA1, int oB0, int oB1){
#pragma unroll
    for (int k = 0; k < KC; k++){
        ulonglong2 b01 = *reinterpret_cast<const ulonglong2*>(Xs + k*512 + oB0);
        ulonglong2 b23 = *reinterpret_cast<const ulonglong2*>(Xs + k*512 + oB1);
        float4 a0 = *reinterpret_cast<const float4*>(Ws + k*512 + oA0);
        float4 a1 = *reinterpret_cast<const float4*>(Ws + k*512 + oA1);
        float av[8] = {a0.x,a0.y,a0.z,a0.w,a1.x,a1.y,a1.z,a1.w};
#pragma unroll
        for (int j = 0; j < 8; j++){
            ull a2 = splat2(av[j]);
            acc[j][0] = ffma2(a2, b01.x, acc[j][0]);
            acc[j][1] = ffma2(a2, b01.y, acc[j][1]);
            acc[j][2] = ffma2(a2, b23.x, acc[j][2]);
            acc[j][3] = ffma2(a2, b23.y, acc[j][3]);
        }
    }
}

// ---------------- weight transposes ----------------
__global__ void k_T_fsm(const float* __restrict__ w){
    int i = blockIdx.x*256 + threadIdx.x;
    if (i < CC*CC){ int o = i >> 7, c = i & 127; g_WT_fsm[c*CC + o] = w[i]; }
}
__global__ void k_T_off(const float* __restrict__ w){   // w: [128][256]
    int i = blockIdx.x*256 + threadIdx.x;
    if (i < CC*2*CC){ int o = i >> 8, c = i & 255; g_WT_off[c*CC + o] = w[i]; }
}
__global__ void k_T_om(const float* __restrict__ w){    // w: [216][128][3][3]
    int i = blockIdx.x*256 + threadIdx.x;
    if (i < KDIM*256){
        int o = i & 255, kidx = i >> 8;
        int tap = kidx >> 7, c = kidx & 127;
        g_WT_om[i] = (o < OMC) ? w[(o*CC + c)*KK9 + tap] : 0.f;
    }
}
__global__ void k_T_dcn(const float* __restrict__ w){   // w: [128][128][3][3]
    int i = blockIdx.x*256 + threadIdx.x;
    if (i < KDIM*CC){
        int o = i & 127, kidx = i >> 7;
        int gk = kidx >> 4, cg = kidx & 15;
        int g = gk/9, kk = gk - g*9;
        int c = g*CG + cg;
        g_WT_dcn[i] = w[(o*CC + c)*KK9 + kk];
    }
}

// ---------------- pooled mean + attention scale ----------------
__global__ void k_pool(const float* __restrict__ fl){
    int bc = blockIdx.x, t = threadIdx.x;
    const float* p = fl + bc*HW;
    float s = 0.f;
    for (int i = t; i < HW; i += 256) s += p[i];
    __shared__ float red[256];
    red[t] = s; __syncthreads();
#pragma unroll
    for (int o = 128; o > 0; o >>= 1){
        if (t < o) red[t] += red[t + o];
        __syncthreads();
    }
    if (t == 0) g_pooled[bc] = red[0] * (1.f/(float)HW);
}
__global__ void k_atten(const float* __restrict__ w_atten){
    int b = blockIdx.x, o = threadIdx.x;
    __shared__ float pl[CC];
    pl[o] = g_pooled[b*CC + o];
    __syncthreads();
    float s = 0.f;
    const float* wr = w_atten + o*CC;
    for (int c = 0; c < CC; c++) s = fmaf(pl[c], wr[c], s);
    s = fmaxf(s, 0.f);
    g_scale[b*CC + o] = 1.f + 1.f/(1.f + __expf(-s));
}

// ---------------- bilinear upsample ----------------
__global__ void k_upsample(const float* __restrict__ fs){
    int idx = blockIdx.x*256 + threadIdx.x;
    int x = idx & 127, y = (idx >> 7) & 127, bc = idx >> 14;
    float fy = y*0.5f - 0.25f, fx = x*0.5f - 0.25f;
    float y0f = floorf(fy), x0f = floorf(fx);
    float wy = fy - y0f, wx = fx - x0f;
    int y0 = (int)y0f, x0 = (int)x0f;
    int y0c = max(y0, 0), y1c = min(y0 + 1, 63);
    int x0c = max(x0, 0), x1c = min(x0 + 1, 63);
    const float* s = fs + bc*4096;
    float v00 = s[y0c*64 + x0c], v01 = s[y0c*64 + x1c];
    float v10 = s[y1c*64 + x0c], v11 = s[y1c*64 + x1c];
    g_feat_up[idx] = (1.f-wy)*((1.f-wx)*v00 + wx*v01) + wy*((1.f-wx)*v10 + wx*v11);
}

// ---------------- GEMM 1: feat_arm = relu(Wfsm @ (feat_l * scale)) ---------
__global__ __launch_bounds__(256,2) void k_gemm_fsm(const float* __restrict__ feat_l){
    __shared__ float Wsm[2][KC*128], Xsm[2][KC*128];
    __shared__ float ssc[CC];
    int y = blockIdx.x, b = blockIdx.y, t = threadIdx.x;
    int to = t >> 4, tp = t & 15, r = to;
    if (t < CC) ssc[t] = g_scale[b*CC + t];
    int oB0 = swz(tp*32), oB1 = swz(tp*32 + 16);
    int oA0 = swz(to*32), oA1 = swz(to*32 + 16);
    ull acc[8][4];
#pragma unroll
    for (int j = 0; j < 8; j++) for (int i = 0; i < 4; i++) acc[j][i] = 0ull;

    const float* wbase = g_WT_fsm + r*128 + tp*8;
    const float* xbase = feat_l + ((b*CC + r)*HH + y)*WWD + tp*8;
    float4 rw0 = *(const float4*)(wbase), rw1 = *(const float4*)(wbase + 4);
    float4 rx0 = *(const float4*)(xbase), rx1 = *(const float4*)(xbase + 4);
    __syncthreads();   // ssc ready

#pragma unroll 1
    for (int c = 0; c < 8; c++){
        int buf = c & 1;
        char* W = (char*)Wsm[buf] + r*512;
        char* X = (char*)Xsm[buf] + r*512;
        *(float4*)(W + oB0) = rw0; *(float4*)(W + oB1) = rw1;
        float sc = ssc[c*KC + r];
        float4 v0 = rx0, v1 = rx1;
        v0.x*=sc; v0.y*=sc; v0.z*=sc; v0.w*=sc;
        v1.x*=sc; v1.y*=sc; v1.z*=sc; v1.w*=sc;
        *(float4*)(X + oB0) = v0; *(float4*)(X + oB1) = v1;
        __syncthreads();
        if (c < 7){
            const float* wp = wbase + (c+1)*KC*128;
            const float* xp = xbase + (c+1)*KC*HW;
            rw0 = *(const float4*)(wp); rw1 = *(const float4*)(wp + 4);
            rx0 = *(const float4*)(xp); rx1 = *(const float4*)(xp + 4);
        }
        mma_chunk((char*)Wsm[buf], (char*)Xsm[buf], acc, oA0, oA1, oB0, oB1);
    }
#pragma unroll
    for (int j = 0; j < 8; j++){
        int o = to*8 + j;
        float2* dst = reinterpret_cast<float2*>(g_feat_arm + ((b*CC+o)*HH + y)*WWD + tp*8);
#pragma unroll
        for (int i2 = 0; i2 < 4; i2++){
            float2 v = unpack2(acc[j][i2]);
            v.x = fmaxf(v.x, 0.f); v.y = fmaxf(v.y, 0.f);
            dst[i2] = v;
        }
    }
}

// ---------------- GEMM 2: offset_feat = relu(Woff @ [feat_arm ; 2*feat_up]) -
__global__ __launch_bounds__(256,2) void k_gemm_off(){
    __shared__ float Wsm[2][KC*128], Xsm[2][KC*128];
    int y = blockIdx.x, b = blockIdx.y, t = threadIdx.x;
    int to = t >> 4, tp = t & 15, r = to;
    int oB0 = swz(tp*32), oB1 = swz(tp*32 + 16);
    int oA0 = swz(to*32), oA1 = swz(to*32 + 16);
    ull acc[8][4];
#pragma unroll
    for (int j = 0; j < 8; j++) for (int i = 0; i < 4; i++) acc[j][i] = 0ull;

    const float* wbase = g_WT_off + r*128 + tp*8;
    auto xptr = [&](int c)->const float*{
        int ch = c*KC + r;
        return (ch < CC) ? g_feat_arm + ((b*CC + ch)*HH + y)*WWD + tp*8
                         : g_feat_up  + ((b*CC + ch - CC)*HH + y)*WWD + tp*8;
    };
    float4 rw0 = *(const float4*)(wbase), rw1 = *(const float4*)(wbase + 4);
    const float* xp0 = xptr(0);
    float4 rx0 = *(const float4*)(xp0), rx1 = *(const float4*)(xp0 + 4);

#pragma unroll 1
    for (int c = 0; c < 16; c++){
        int buf = c & 1;
        char* W = (char*)Wsm[buf] + r*512;
        char* X = (char*)Xsm[buf] + r*512;
        *(float4*)(W + oB0) = rw0; *(float4*)(W + oB1) = rw1;
        float sc = (c < 8) ? 1.f : 2.f;
        float4 v0 = rx0, v1 = rx1;
        v0.x*=sc; v0.y*=sc; v0.z*=sc; v0.w*=sc;
        v1.x*=sc; v1.y*=sc; v1.z*=sc; v1.w*=sc;
        *(float4*)(X + oB0) = v0; *(float4*)(X + oB1) = v1;
        __syncthreads();
        if (c < 15){
            const float* wp = wbase + (c+1)*KC*128;
            const float* xp = xptr(c+1);
            rw0 = *(const float4*)(wp); rw1 = *(const float4*)(wp + 4);
            rx0 = *(const float4*)(xp); rx1 = *(const float4*)(xp + 4);
        }
        mma_chunk((char*)Wsm[buf], (char*)Xsm[buf], acc, oA0, oA1, oB0, oB1);
    }
#pragma unroll
    for (int j = 0; j < 8; j++){
        int o = to*8 + j;
        float2* dst = reinterpret_cast<float2*>(g_offf + ((b*CC+o)*HH + y)*WWD + tp*8);
#pragma unroll
        for (int i2 = 0; i2 < 4; i2++){
            float2 v = unpack2(acc[j][i2]);
            v.x = fmaxf(v.x, 0.f); v.y = fmaxf(v.y, 0.f);
            dst[i2] = v;
        }
    }
}

// ---------------- GEMM 3: conv_offset_mask (implicit shifted GEMM) ----------
__global__ __launch_bounds__(256,2) void k_gemm_om(const float* __restrict__ b_offmask){
    __shared__ float Wsm[2][KC*128], Xsm[2][KC*128];
    int y = blockIdx.x, b = blockIdx.y, t = threadIdx.x;
    int o0 = blockIdx.z * 128;
    int to = t >> 4, tp = t & 15, r = to;
    int oB0 = swz(tp*32), oB1 = swz(tp*32 + 16);
    int oA0 = swz(to*32), oA1 = swz(to*32 + 16);
    ull acc[8][4];
#pragma unroll
    for (int j = 0; j < 8; j++) for (int i = 0; i < 4; i++) acc[j][i] = 0ull;

    float4 rw0, rw1;
    float rx[8];
    auto prefetch = [&](int c){
        const float* wp = g_WT_om + (c*KC + r)*256 + o0 + tp*8;
        rw0 = *(const float4*)(wp); rw1 = *(const float4*)(wp + 4);
        int tap = c >> 3;
        int ty = tap/3 - 1, tx = tap - (tap/3)*3 - 1;
        int ch = (c & 7)*16 + r;
        int gy = y + ty;
        bool rowok = (gy >= 0) && (gy < HH);
        const float* rowp = g_offf + ((b*CC + ch)*HH + gy)*WWD;
#pragma unroll
        for (int i = 0; i < 8; i++){
            int gx = tp*8 + i + tx;
            rx[i] = (rowok && gx >= 0 && gx < WWD) ? rowp[gx] : 0.f;
        }
    };
    prefetch(0);

#pragma unroll 1
    for (int c = 0; c < 72; c++){
        int buf = c & 1;
        char* W = (char*)Wsm[buf] + r*512;
        char* X = (char*)Xsm[buf] + r*512;
        *(float4*)(W + oB0) = rw0; *(float4*)(W + oB1) = rw1;
        *(float4*)(X + oB0) = make_float4(rx[0], rx[1], rx[2], rx[3]);
        *(float4*)(X + oB1) = make_float4(rx[4], rx[5], rx[6], rx[7]);
        __syncthreads();
        if (c < 71) prefetch(c+1);
        mma_chunk((char*)Wsm[buf], (char*)Xsm[buf], acc, oA0, oA1, oB0, oB1);
    }
#pragma unroll
    for (int j = 0; j < 8; j++){
        int o = o0 + to*8 + j;
        if (o < OMC){
            float bias = b_offmask[o];
            float2* dst = reinterpret_cast<float2*>(g_om + (b*OMC + o)*HW + y*WWD + tp*8);
#pragma unroll
            for (int i2 = 0; i2 < 4; i2++){
                float2 v = unpack2(acc[j][i2]);
                v.x += bias; v.y += bias;
                dst[i2] = v;
            }
        }
    }
}

// ---------------- GEMM 4: modulated deformable conv + relu + residual -------
__global__ __launch_bounds__(256,2) void k_gemm_dcn(const float* __restrict__ feat_l,
                                                    const float* __restrict__ b_dcn,
                                                    float* __restrict__ out){
    __shared__ float Wsm[2][KC*128], Xsm[2][KC*128];
    __shared__ float4 swt[2][128];
    __shared__ int4  sof[2][128];
    int y = blockIdx.x, b = blockIdx.y, t = threadIdx.x;
    int to = t >> 4, tp = t & 15, r = to;
    int oB0 = swz(tp*32), oB1 = swz(tp*32 + 16);
    int oA0 = swz(to*32), oA1 = swz(to*32 + 16);
    ull acc[8][4];
#pragma unroll
    for (int j = 0; j < 8; j++) for (int i = 0; i < 4; i++) acc[j][i] = 0ull;

    // per-pixel param-array swizzled index (bank-conflict-free gather reads)
    int xs_self = t ^ ((t >> 3) & 7);        // for t<128 writers
    const float* omp = g_om + b*OMC*HW + y*WWD + (t & 127);

    float rom0 = 0.f, rom1 = 0.f, rom2 = 0.f;
    auto load_rom = [&](int m){
        int g = m/9, kk = m - 9*g;
        rom0 = omp[(g*18 + kk*2    )*HW];
        rom1 = omp[(g*18 + kk*2 + 1)*HW];
        rom2 = omp[(144 + g*9 + kk )*HW];
    };
    auto calc_params = [&](int m, int pbuf){
        int g = m/9, kk = m - 9*g; (void)g;
        int x = t;
        float mval = 1.f/(1.f + __expf(-rom2));
        float py = (float)(y + kk/3 - 1) + rom0;
        float px = (float)(x + (kk - (kk/3)*3) - 1) + rom1;
        float y0f = floorf(py), x0f = floorf(px);
        float ly = py - y0f, lx = px - x0f;
        int y0 = (int)y0f, x0 = (int)x0f;
        float vy0 = (y0 >=  0 && y0 < HH    ) ? 1.f : 0.f;
        float vy1 = (y0 >= -1 && y0 < HH - 1) ? 1.f : 0.f;
        float vx0 = (x0 >=  0 && x0 < WWD    ) ? 1.f : 0.f;
        float vx1 = (x0 >= -1 && x0 < WWD - 1) ? 1.f : 0.f;
        float omy = 1.f - ly, omx = 1.f - lx;
        float4 w;
        w.x = omy*omx*vy0*vx0*mval;
        w.y = omy*lx *vy0*vx1*mval;
        w.z = ly *omx*vy1*vx0*mval;
        w.w = ly *lx *vy1*vx1*mval;
        int y0c = min(max(y0,0),HH-1),   y1c = min(max(y0+1,0),HH-1);
        int x0c = min(max(x0,0),WWD-1),  x1c = min(max(x0+1,0),WWD-1);
        sof[pbuf][xs_self] = make_int4(y0c*WWD + x0c, y0c*WWD + x1c,
                                       y1c*WWD + x0c, y1c*WWD + x1c);
        swt[pbuf][xs_self] = w;
    };

    float4 rw0, rw1;
    float rx[8];
    auto prefetch_w = [&](int m){
        const float* wp = g_WT_dcn + (m*16 + r)*128 + tp*8;
        rw0 = *(const float4*)(wp); rw1 = *(const float4*)(wp + 4);
    };
    auto gather = [&](int m, int pbuf){
        int g = m/9;
        const float* fp = g_feat_up + (b*CC + g*CG + r)*HW;
#pragma unroll
        for (int i = 0; i < 8; i++){
            int px = tp*8 + i;
            int pidx = px ^ ((px >> 3) & 7);
            int4  o4 = sof[pbuf][pidx];
            float4 w4 = swt[pbuf][pidx];
            rx[i] = w4.x*fp[o4.x] + w4.y*fp[o4.y] + w4.z*fp[o4.z] + w4.w*fp[o4.w];
        }
    };

    // pre-loop: params(0) -> pb[0]; rom holds chunk 1
    if (t < 128){
        load_rom(0);
        calc_params(0, 0);
        load_rom(1);
    }
    prefetch_w(0);
    __syncthreads();
    gather(0, 0);

#pragma unroll 1
    for (int c = 0; c < 72; c++){
        int buf = c & 1;
        char* W = (char*)Wsm[buf] + r*512;
        char* X = (char*)Xsm[buf] + r*512;
        *(float4*)(W + oB0) = rw0; *(float4*)(W + oB1) = rw1;
        *(float4*)(X + oB0) = make_float4(rx[0], rx[1], rx[2], rx[3]);
        *(float4*)(X + oB1) = make_float4(rx[4], rx[5], rx[6], rx[7]);
        __syncthreads();                              // sync1: tiles(c) ready
        if (c + 1 < 72){
            if (t < 128) calc_params(c+1, (c+1) & 1); // from rom (chunk c+1)
            prefetch_w(c+1);
            if (t < 128 && c + 2 < 72) load_rom(c+2);
        }
        __syncthreads();                              // sync2: params(c+1) ready
        if (c + 1 < 72) gather(c+1, (c+1) & 1);
        mma_chunk((char*)Wsm[buf], (char*)Xsm[buf], acc, oA0, oA1, oB0, oB1);
    }

#pragma unroll
    for (int j = 0; j < 8; j++){
        int o = to*8 + j;
        float bias = b_dcn[o];
        int base = ((b*CC + o)*HH + y)*WWD + tp*8;
        const float2* flp = reinterpret_cast<const float2*>(feat_l + base);
        float2* dst = reinterpret_cast<float2*>(out + base);
#pragma unroll
        for (int i2 = 0; i2 < 4; i2++){
            float2 v  = unpack2(acc[j][i2]);
            float2 fl = flp[i2];
            v.x = fmaxf(v.x + bias, 0.f) + fl.x;
            v.y = fmaxf(v.y + bias, 0.f) + fl.y;
            dst[i2] = v;
        }
    }
}

// ---------------- launcher ----------------
extern "C" void kernel_launch(void* const* d_in, const int* in_sizes, int n_in,
                              void* d_out, int out_size){
    (void)in_sizes; (void)n_in; (void)out_size;
    const float* feat_l    = (const float*)d_in[0];
    const float* feat_s    = (const float*)d_in[1];
    const float* w_atten   = (const float*)d_in[2];
    const float* w_fsm     = (const float*)d_in[3];
    const float* w_off     = (const float*)d_in[4];
    const float* w_offmask = (const float*)d_in[5];
    const float* b_offmask = (const float*)d_in[6];
    const float* w_dcn     = (const float*)d_in[7];
    const float* b_dcn     = (const float*)d_in[8];
    float* out = (float*)d_out;

    // order chosen so the ncu-captured launch (idx 3) is a real GEMM
    k_T_fsm<<<64, 256>>>(w_fsm);
    k_pool<<<BB*CC, 256>>>(feat_l);
    k_atten<<<BB, CC>>>(w_atten);
    k_gemm_fsm<<<dim3(HH, BB), 256>>>(feat_l);
    k_T_off<<<128, 256>>>(w_off);
    k_T_om<<<1152, 256>>>(w_offmask);
    k_T_dcn<<<576, 256>>>(w_dcn);
    k_upsample<<<(BB*CC*HW)/256, 256>>>(feat_s);
    k_gemm_off<<<dim3(HH, BB), 256>>>();
    k_gemm_om<<<dim3(HH, BB, 2), 256>>>(b_offmask);
    k_gemm_dcn<<<dim3(HH, BB), 256>>>(feat_l, b_dcn, out);
}

// round 11
// speedup vs baseline: 2.4841x; 1.0154x over previous
#include <cuda_runtime.h>

#define BB 2
#define CC 128
#define HH 128
#define WWD 128
#define HW 16384
#define GG 8
#define CG 16
#define KK9 9
#define OMC 216
#define KDIM 1152
#define KC 16

typedef unsigned long long ull;

// ---------------- static scratch ----------------
__device__ float g_feat_up [BB*CC*HW];
__device__ float g_feat_arm[BB*CC*HW];
__device__ float g_offf    [BB*CC*HW];
__device__ float g_om      [BB*OMC*HW];
__device__ float g_pooled  [BB*CC];
__device__ float g_scale   [BB*CC];
__device__ float g_WT_fsm2 [BB*CC*CC];     // [b][c][o], scale folded
__device__ float g_WT_off  [2*CC*CC];      // [c][o], x2 folded for c>=128
__device__ float g_WT_om   [KDIM*256];     // [tap*128+c][o pad 256]
__device__ float g_WT_dcn  [KDIM*CC];      // [(g*9+kk)*16+cg][o]

// ---------------- helpers ----------------
__device__ __forceinline__ ull ffma2(ull a, ull b, ull c){
    ull d;
    asm("fma.rn.f32x2 %0, %1, %2, %3;" : "=l"(d) : "l"(a), "l"(b), "l"(c));
    return d;
}
__device__ __forceinline__ ull splat2(float a){
    ull d;
    asm("mov.b64 %0, {%1, %1};" : "=l"(d) : "f"(a));
    return d;
}
__device__ __forceinline__ float2 unpack2(ull v){
    float2 r;
    asm("mov.b64 {%0, %1}, %2;" : "=f"(r.x), "=f"(r.y) : "l"(v));
    return r;
}
__device__ __forceinline__ int swz(int b){ return b ^ ((b >> 3) & 16); }

__device__ __forceinline__ unsigned su32(const void* p){
    return (unsigned)__cvta_generic_to_shared(p);
}
__device__ __forceinline__ void cp16(unsigned s, const void* g){
    asm volatile("cp.async.cg.shared.global [%0], [%1], 16;" :: "r"(s), "l"(g));
}
#define CP_COMMIT asm volatile("cp.async.commit_group;")
#define CP_WAIT0  asm volatile("cp.async.wait_group 0;")

// ---------------- inner MMA: 128o x 128p, K-chunk 16, swizzled smem ---------
__device__ __forceinline__ void mma_chunk(const char* __restrict__ Ws,
                                          const char* __restrict__ Xs,
                                          ull acc[8][4],
                                          int oA0, int oA1, int oB0, int oB1){
#pragma unroll
    for (int k = 0; k < KC; k++){
        ulonglong2 b01 = *reinterpret_cast<const ulonglong2*>(Xs + k*512 + oB0);
        ulonglong2 b23 = *reinterpret_cast<const ulonglong2*>(Xs + k*512 + oB1);
        float4 a0 = *reinterpret_cast<const float4*>(Ws + k*512 + oA0);
        float4 a1 = *reinterpret_cast<const float4*>(Ws + k*512 + oA1);
        float av[8] = {a0.x,a0.y,a0.z,a0.w,a1.x,a1.y,a1.z,a1.w};
#pragma unroll
        for (int j = 0; j < 8; j++){
            ull a2 = splat2(av[j]);
            acc[j][0] = ffma2(a2, b01.x, acc[j][0]);
            acc[j][1] = ffma2(a2, b01.y, acc[j][1]);
            acc[j][2] = ffma2(a2, b23.x, acc[j][2]);
            acc[j][3] = ffma2(a2, b23.y, acc[j][3]);
        }
    }
}

// ---------------- weight transposes ----------------
__global__ void k_T_fsm2(const float* __restrict__ w){   // needs g_scale
    int i = blockIdx.x*256 + threadIdx.x;                // dst [b][c][o]
    if (i < BB*CC*CC){
        int b = i >> 14, c = (i >> 7) & 127, o = i & 127;
        g_WT_fsm2[i] = w[o*CC + c] * g_scale[b*CC + c];
    }
}
__global__ void k_T_off(const float* __restrict__ w){    // w: [128][256]
    int i = blockIdx.x*256 + threadIdx.x;                // dst [c][o]
    if (i < 2*CC*CC){
        int c = i >> 7, o = i & 127;
        float f = (c < CC) ? 1.f : 2.f;
        g_WT_off[i] = w[o*2*CC + c] * f;
    }
}
__global__ void k_T_om(const float* __restrict__ w){     // w: [216][128][3][3]
    int i = blockIdx.x*256 + threadIdx.x;
    if (i < KDIM*256){
        int o = i & 255, kidx = i >> 8;
        int tap = kidx >> 7, c = kidx & 127;
        g_WT_om[i] = (o < OMC) ? w[(o*CC + c)*KK9 + tap] : 0.f;
    }
}
__global__ void k_T_dcn(const float* __restrict__ w){    // w: [128][128][3][3]
    int i = blockIdx.x*256 + threadIdx.x;
    if (i < KDIM*CC){
        int o = i & 127, kidx = i >> 7;
        int gk = kidx >> 4, cg = kidx & 15;
        int g = gk/9, kk = gk - g*9;
        int c = g*CG + cg;
        g_WT_dcn[i] = w[(o*CC + c)*KK9 + kk];
    }
}

// ---------------- pooled mean + attention scale ----------------
__global__ void k_pool(const float* __restrict__ fl){
    int bc = blockIdx.x, t = threadIdx.x;
    const float* p = fl + bc*HW;
    float s = 0.f;
    for (int i = t; i < HW; i += 256) s += p[i];
    __shared__ float red[256];
    red[t] = s; __syncthreads();
#pragma unroll
    for (int o = 128; o > 0; o >>= 1){
        if (t < o) red[t] += red[t + o];
        __syncthreads();
    }
    if (t == 0) g_pooled[bc] = red[0] * (1.f/(float)HW);
}
__global__ void k_atten(const float* __restrict__ w_atten){
    int b = blockIdx.x, o = threadIdx.x;
    __shared__ float pl[CC];
    pl[o] = g_pooled[b*CC + o];
    __syncthreads();
    float s = 0.f;
    const float* wr = w_atten + o*CC;
    for (int c = 0; c < CC; c++) s = fmaf(pl[c], wr[c], s);
    s = fmaxf(s, 0.f);
    g_scale[b*CC + o] = 1.f + 1.f/(1.f + __expf(-s));
}

// ---------------- bilinear upsample ----------------
__global__ void k_upsample(const float* __restrict__ fs){
    int idx = blockIdx.x*256 + threadIdx.x;
    int x = idx & 127, y = (idx >> 7) & 127, bc = idx >> 14;
    float fy = y*0.5f - 0.25f, fx = x*0.5f - 0.25f;
    float y0f = floorf(fy), x0f = floorf(fx);
    float wy = fy - y0f, wx = fx - x0f;
    int y0 = (int)y0f, x0 = (int)x0f;
    int y0c = max(y0, 0), y1c = min(y0 + 1, 63);
    int x0c = max(x0, 0), x1c = min(x0 + 1, 63);
    const float* s = fs + bc*4096;
    float v00 = s[y0c*64 + x0c], v01 = s[y0c*64 + x1c];
    float v10 = s[y1c*64 + x0c], v11 = s[y1c*64 + x1c];
    g_feat_up[idx] = (1.f-wy)*((1.f-wx)*v00 + wx*v01) + wy*((1.f-wx)*v10 + wx*v11);
}

// ---------------- GEMM 1: feat_arm = relu(Wfsm' @ feat_l) ----------------
__global__ __launch_bounds__(256,2) void k_gemm_fsm(const float* __restrict__ feat_l){
    __shared__ float Wsm[2][KC*128], Xsm[2][KC*128];
    int y = blockIdx.x, b = blockIdx.y, t = threadIdx.x;
    int to = t >> 4, tp = t & 15, r = to;
    int oB0 = swz(tp*32), oB1 = swz(tp*32 + 16);
    int oA0 = swz(to*32), oA1 = swz(to*32 + 16);
    ull acc[8][4];
#pragma unroll
    for (int j = 0; j < 8; j++) for (int i = 0; i < 4; i++) acc[j][i] = 0ull;

    const float* wbase = g_WT_fsm2 + b*CC*CC + r*128 + tp*8;
    const float* xbase = feat_l + ((b*CC + r)*HH + y)*WWD + tp*8;

    auto stage = [&](int c){
        int buf = c & 1;
        unsigned wd = su32((char*)Wsm[buf] + r*512);
        unsigned xd = su32((char*)Xsm[buf] + r*512);
        cp16(wd + oB0, wbase + c*KC*128);
        cp16(wd + oB1, wbase + c*KC*128 + 4);
        cp16(xd + oB0, xbase + c*KC*HW);
        cp16(xd + oB1, xbase + c*KC*HW + 4);
        CP_COMMIT;
    };
    stage(0);
#pragma unroll 1
    for (int c = 0; c < 8; c++){
        CP_WAIT0;
        __syncthreads();
        if (c < 7) stage(c+1);
        mma_chunk((char*)Wsm[c&1], (char*)Xsm[c&1], acc, oA0, oA1, oB0, oB1);
    }
#pragma unroll
    for (int j = 0; j < 8; j++){
        int o = to*8 + j;
        float2* dst = reinterpret_cast<float2*>(g_feat_arm + ((b*CC+o)*HH + y)*WWD + tp*8);
#pragma unroll
        for (int i2 = 0; i2 < 4; i2++){
            float2 v = unpack2(acc[j][i2]);
            v.x = fmaxf(v.x, 0.f); v.y = fmaxf(v.y, 0.f);
            dst[i2] = v;
        }
    }
}

// ---------------- GEMM 2: offset_feat = relu(Woff' @ [feat_arm ; feat_up]) --
__global__ __launch_bounds__(256,2) void k_gemm_off(){
    __shared__ float Wsm[2][KC*128], Xsm[2][KC*128];
    int y = blockIdx.x, b = blockIdx.y, t = threadIdx.x;
    int to = t >> 4, tp = t & 15, r = to;
    int oB0 = swz(tp*32), oB1 = swz(tp*32 + 16);
    int oA0 = swz(to*32), oA1 = swz(to*32 + 16);
    ull acc[8][4];
#pragma unroll
    for (int j = 0; j < 8; j++) for (int i = 0; i < 4; i++) acc[j][i] = 0ull;

    const float* wbase = g_WT_off + r*128 + tp*8;
    auto stage = [&](int c){
        int buf = c & 1;
        unsigned wd = su32((char*)Wsm[buf] + r*512);
        unsigned xd = su32((char*)Xsm[buf] + r*512);
        cp16(wd + oB0, wbase + c*KC*128);
        cp16(wd + oB1, wbase + c*KC*128 + 4);
        int ch = c*KC + r;
        const float* xp = (ch < CC) ? g_feat_arm + ((b*CC + ch)*HH + y)*WWD + tp*8
                                    : g_feat_up  + ((b*CC + ch - CC)*HH + y)*WWD + tp*8;
        cp16(xd + oB0, xp);
        cp16(xd + oB1, xp + 4);
        CP_COMMIT;
    };
    stage(0);
#pragma unroll 1
    for (int c = 0; c < 16; c++){
        CP_WAIT0;
        __syncthreads();
        if (c < 15) stage(c+1);
        mma_chunk((char*)Wsm[c&1], (char*)Xsm[c&1], acc, oA0, oA1, oB0, oB1);
    }
#pragma unroll
    for (int j = 0; j < 8; j++){
        int o = to*8 + j;
        float2* dst = reinterpret_cast<float2*>(g_offf + ((b*CC+o)*HH + y)*WWD + tp*8);
#pragma unroll
        for (int i2 = 0; i2 < 4; i2++){
            float2 v = unpack2(acc[j][i2]);
            v.x = fmaxf(v.x, 0.f); v.y = fmaxf(v.y, 0.f);
            dst[i2] = v;
        }
    }
}

// ---------------- GEMM 3: conv_offset_mask (implicit shifted GEMM) ----------
__global__ __launch_bounds__(256,2) void k_gemm_om(const float* __restrict__ b_offmask){
    __shared__ float Wsm[2][KC*128], Xsm[2][KC*128];
    int y = blockIdx.x, b = blockIdx.y, t = threadIdx.x;
    int o0 = blockIdx.z * 128;
    int to = t >> 4, tp = t & 15, r = to;
    int oB0 = swz(tp*32), oB1 = swz(tp*32 + 16);
    int oA0 = swz(to*32), oA1 = swz(to*32 + 16);
    bool act = (o0 + to*8) < OMC;       // skip padded outputs (slab 2)
    ull acc[8][4];
#pragma unroll
    for (int j = 0; j < 8; j++) for (int i = 0; i < 4; i++) acc[j][i] = 0ull;

    auto stageW = [&](int c){
        int buf = c & 1;
        unsigned wd = su32((char*)Wsm[buf] + r*512);
        const float* wp = g_WT_om + (c*KC + r)*256 + o0 + tp*8;
        cp16(wd + oB0, wp);
        cp16(wd + oB1, wp + 4);
        CP_COMMIT;
    };
    float rx[8];
    auto prefX = [&](int c){
        int tap = c >> 3;
        int ty = tap/3 - 1, tx = tap - (tap/3)*3 - 1;
        int ch = (c & 7)*16 + r;
        int gy = y + ty;
        bool rowok = (gy >= 0) && (gy < HH);
        const float* rowp = g_offf + ((b*CC + ch)*HH + gy)*WWD;
#pragma unroll
        for (int i = 0; i < 8; i++){
            int gx = tp*8 + i + tx;
            rx[i] = (rowok && gx >= 0 && gx < WWD) ? rowp[gx] : 0.f;
        }
    };
    stageW(0);
    prefX(0);
#pragma unroll 1
    for (int c = 0; c < 72; c++){
        int buf = c & 1;
        char* X = (char*)Xsm[buf] + r*512;
        *(float4*)(X + oB0) = make_float4(rx[0], rx[1], rx[2], rx[3]);
        *(float4*)(X + oB1) = make_float4(rx[4], rx[5], rx[6], rx[7]);
        CP_WAIT0;
        __syncthreads();
        if (c < 71){ stageW(c+1); prefX(c+1); }
        if (act) mma_chunk((char*)Wsm[buf], (char*)Xsm[buf], acc, oA0, oA1, oB0, oB1);
    }
#pragma unroll
    for (int j = 0; j < 8; j++){
        int o = o0 + to*8 + j;
        if (o < OMC){
            float bias = b_offmask[o];
            float2* dst = reinterpret_cast<float2*>(g_om + (b*OMC + o)*HW + y*WWD + tp*8);
#pragma unroll
            for (int i2 = 0; i2 < 4; i2++){
                float2 v = unpack2(acc[j][i2]);
                v.x += bias; v.y += bias;
                dst[i2] = v;
            }
        }
    }
}

// ---------------- GEMM 4: modulated deformable conv + relu + residual -------
__global__ __launch_bounds__(256,2) void k_gemm_dcn(const float* __restrict__ feat_l,
                                                    const float* __restrict__ b_dcn,
                                                    float* __restrict__ out){
    __shared__ float Wsm[2][KC*128], Xsm[2][KC*128];
    __shared__ float4 swt[2][128];
    __shared__ int4  sof[2][128];
    int y = blockIdx.x, b = blockIdx.y, t = threadIdx.x;
    int to = t >> 4, tp = t & 15, r = to;
    int oB0 = swz(tp*32), oB1 = swz(tp*32 + 16);
    int oA0 = swz(to*32), oA1 = swz(to*32 + 16);
    ull acc[8][4];
#pragma unroll
    for (int j = 0; j < 8; j++) for (int i = 0; i < 4; i++) acc[j][i] = 0ull;

    int xs_self = t ^ ((t >> 3) & 7);
    const float* omp = g_om + b*OMC*HW + y*WWD + (t & 127);

    float rom0 = 0.f, rom1 = 0.f, rom2 = 0.f;
    auto load_rom = [&](int m){
        int g = m/9, kk = m - 9*g;
        rom0 = omp[(g*18 + kk*2    )*HW];
        rom1 = omp[(g*18 + kk*2 + 1)*HW];
        rom2 = omp[(144 + g*9 + kk )*HW];
    };
    auto calc_params = [&](int m, int pbuf){
        int kk = m - 9*(m/9);
        int x = t;
        float mval = 1.f/(1.f + __expf(-rom2));
        float py = (float)(y + kk/3 - 1) + rom0;
        float px = (float)(x + (kk - (kk/3)*3) - 1) + rom1;
        float y0f = floorf(py), x0f = floorf(px);
        float ly = py - y0f, lx = px - x0f;
        int y0 = (int)y0f, x0 = (int)x0f;
        float vy0 = (y0 >=  0 && y0 < HH    ) ? 1.f : 0.f;
        float vy1 = (y0 >= -1 && y0 < HH - 1) ? 1.f : 0.f;
        float vx0 = (x0 >=  0 && x0 < WWD    ) ? 1.f : 0.f;
        float vx1 = (x0 >= -1 && x0 < WWD - 1) ? 1.f : 0.f;
        float omy = 1.f - ly, omx = 1.f - lx;
        float4 w;
        w.x = omy*omx*vy0*vx0*mval;
        w.y = omy*lx *vy0*vx1*mval;
        w.z = ly *omx*vy1*vx0*mval;
        w.w = ly *lx *vy1*vx1*mval;
        int y0c = min(max(y0,0),HH-1),   y1c = min(max(y0+1,0),HH-1);
        int x0c = min(max(x0,0),WWD-1),  x1c = min(max(x0+1,0),WWD-1);
        sof[pbuf][xs_self] = make_int4(y0c*WWD + x0c, y0c*WWD + x1c,
                                       y1c*WWD + x0c, y1c*WWD + x1c);
        swt[pbuf][xs_self] = w;
    };
    auto stageW = [&](int m){
        int buf = m & 1;
        unsigned wd = su32((char*)Wsm[buf] + r*512);
        const float* wp = g_WT_dcn + (m*16 + r)*128 + tp*8;
        cp16(wd + oB0, wp);
        cp16(wd + oB1, wp + 4);
        CP_COMMIT;
    };
    float rx[8];
    auto gather = [&](int m, int pbuf){
        int g = m/9;
        const float* fp = g_feat_up + (b*CC + g*CG + r)*HW;
#pragma unroll
        for (int i = 0; i < 8; i++){
            int px = tp*8 + i;
            int pidx = px ^ ((px >> 3) & 7);
            int4  o4 = sof[pbuf][pidx];
            float4 w4 = swt[pbuf][pidx];
            rx[i] = w4.x*fp[o4.x] + w4.y*fp[o4.y] + w4.z*fp[o4.z] + w4.w*fp[o4.w];
        }
    };

    if (t < 128){
        load_rom(0);
        calc_params(0, 0);
        load_rom(1);
    }
    stageW(0);
    __syncthreads();
    gather(0, 0);

#pragma unroll 1
    for (int c = 0; c < 72; c++){
        int buf = c & 1;
        char* X = (char*)Xsm[buf] + r*512;
        *(float4*)(X + oB0) = make_float4(rx[0], rx[1], rx[2], rx[3]);
        *(float4*)(X + oB1) = make_float4(rx[4], rx[5], rx[6], rx[7]);
        CP_WAIT0;
        __syncthreads();                              // X(c), W(c) ready
        if (c + 1 < 72){
            stageW(c+1);
            if (t < 128) calc_params(c+1, (c+1) & 1);
            if (t < 128 && c + 2 < 72) load_rom(c+2);
        }
        __syncthreads();                              // params(c+1) ready
        if (c + 1 < 72) gather(c+1, (c+1) & 1);
        mma_chunk((char*)Wsm[buf], (char*)Xsm[buf], acc, oA0, oA1, oB0, oB1);
    }

#pragma unroll
    for (int j = 0; j < 8; j++){
        int o = to*8 + j;
        float bias = b_dcn[o];
        int base = ((b*CC + o)*HH + y)*WWD + tp*8;
        const float2* flp = reinterpret_cast<const float2*>(feat_l + base);
        float2* dst = reinterpret_cast<float2*>(out + base);
#pragma unroll
        for (int i2 = 0; i2 < 4; i2++){
            float2 v  = unpack2(acc[j][i2]);
            float2 fl = flp[i2];
            v.x = fmaxf(v.x + bias, 0.f) + fl.x;
            v.y = fmaxf(v.y + bias, 0.f) + fl.y;
            dst[i2] = v;
        }
    }
}

// ---------------- launcher ----------------
extern "C" void kernel_launch(void* const* d_in, const int* in_sizes, int n_in,
                              void* d_out, int out_size){
    (void)in_sizes; (void)n_in; (void)out_size;
    const float* feat_l    = (const float*)d_in[0];
    const float* feat_s    = (const float*)d_in[1];
    const float* w_atten   = (const float*)d_in[2];
    const float* w_fsm     = (const float*)d_in[3];
    const float* w_off     = (const float*)d_in[4];
    const float* w_offmask = (const float*)d_in[5];
    const float* b_offmask = (const float*)d_in[6];
    const float* w_dcn     = (const float*)d_in[7];
    const float* b_dcn     = (const float*)d_in[8];
    float* out = (float*)d_out;

    // ncu profiles launch idx 3 (0-based) -> keep k_gemm_fsm there
    k_pool<<<BB*CC, 256>>>(feat_l);
    k_atten<<<BB, CC>>>(w_atten);
    k_T_fsm2<<<128, 256>>>(w_fsm);
    k_gemm_fsm<<<dim3(HH, BB), 256>>>(feat_l);
    k_upsample<<<(BB*CC*HW)/256, 256>>>(feat_s);
    k_T_off<<<128, 256>>>(w_off);
    k_T_om<<<1152, 256>>>(w_offmask);
    k_T_dcn<<<576, 256>>>(w_dcn);
    k_gemm_off<<<dim3(HH, BB), 256>>>();
    k_gemm_om<<<dim3(HH, BB, 2), 256>>>(b_offmask);
    k_gemm_dcn<<<dim3(HH, BB), 256>>>(feat_l, b_dcn, out);
}